// round 12
// baseline (speedup 1.0000x reference)
#include <cuda_runtime.h>
#include <math_constants.h>
#include <cstdint>

#define BB 8
#define CC 256
#define HH 128
#define WW 128
#define HW (HH*WW)
#define TOPK 10
#define THRESH 0.5f
#define MARGIN 0.5f
#define EPSV 1e-8f
#define NMAPS 16
#define JCTAS 8
#define JROWS 16
#define JPIX (JROWS*WW)
#define PADW 130
#define STG_ROWS 18
#define T2 256

// ---- TMA stream pipeline config ----
#define PIX_PER_CTA 1024           // 4KB per channel slice
#define SLICES 16                  // 16384 / 1024
#define STAGES 3
#define CHPST 8                    // channels per stage
#define STAGE_BYTES (CHPST * PIX_PER_CTA * 4)   // 32KB
#define NSTG (CC / CHPST)          // 32 stage-iterations
#define SMEM_STREAM (STAGES * STAGE_BYTES + 64) // + mbarriers

// scratch (no allocations allowed); counters self-reset -> replay-safe
__device__ float    g_intensity[NMAPS][HW];
__device__ float    g_part_val[NMAPS][JCTAS][TOPK];
__device__ int      g_part_idx[NMAPS][JCTAS][TOPK];
__device__ float    g_losses[BB];
__device__ unsigned g_samp_cnt[BB];
__device__ unsigned g_done_cnt;

__device__ __forceinline__ uint32_t smem_u32(const void* p) {
    uint32_t a;
    asm("{ .reg .u64 t; cvta.to.shared.u64 t, %1; cvt.u32.u64 %0, t; }"
        : "=r"(a) : "l"(p));
    return a;
}

__device__ __forceinline__ void mbar_init(uint32_t bar, uint32_t cnt) {
    asm volatile("mbarrier.init.shared.b64 [%0], %1;" :: "r"(bar), "r"(cnt) : "memory");
}
__device__ __forceinline__ void mbar_expect_tx(uint32_t bar, uint32_t bytes) {
    asm volatile("mbarrier.arrive.expect_tx.shared.b64 _, [%0], %1;"
                 :: "r"(bar), "r"(bytes) : "memory");
}
__device__ __forceinline__ void mbar_wait(uint32_t bar, uint32_t parity) {
    asm volatile(
        "{\n\t.reg .pred P;\n\t"
        "WL%=:\n\t"
        "mbarrier.try_wait.parity.acquire.cta.shared::cta.b64 P, [%0], %1, 0x989680;\n\t"
        "@!P bra WL%=;\n\t}"
        :: "r"(bar), "r"(parity) : "memory");
}
__device__ __forceinline__ void bulk_ld(uint32_t dst, const void* src,
                                        uint32_t bytes, uint32_t bar) {
    asm volatile(
        "cp.async.bulk.shared::cluster.global.mbarrier::complete_tx::bytes "
        "[%0], [%1], %2, [%3];"
        :: "r"(dst), "l"(src), "r"(bytes), "r"(bar) : "memory");
}

// ---------------------------------------------------------------------------
// Kernel 1: TMA-pipelined intensity stream. 256 CTAs x 256 thr, ~96KB smem.
// In-flight bytes now live in SMEM (2-3 x 32KB stages), not registers:
// >100KB/SM outstanding vs the ~32KB needed for 8TB/s. LDG-based MLP peaked
// at ~4.1TB/s across R7/R8/R11 regardless of warps/batching/regs.
// ---------------------------------------------------------------------------
extern __shared__ __align__(128) unsigned char smraw[];
__global__ void __launch_bounds__(256) stream_kernel(
    const float* __restrict__ det, const float* __restrict__ loc)
{
    const int bid = blockIdx.x;          // 0..255
    const int m   = bid >> 4;            // map 0..15 (0..7 det, 8..15 loc)
    const int s   = bid & 15;            // pixel slice
    const int b   = m & 7;
    const int tid = threadIdx.x;

    const float* src = ((m < 8) ? det : loc)
                       + (size_t)b * CC * HW + (size_t)s * PIX_PER_CTA;

    const uint32_t smem_base = smem_u32(smraw);
    const uint32_t mbar0 = smem_base + STAGES * STAGE_BYTES;

    if (tid == 0) {
        #pragma unroll
        for (int k = 0; k < STAGES; k++) mbar_init(mbar0 + k * 8, 1u);
        asm volatile("fence.proxy.async.shared::cta;" ::: "memory");
    }
    __syncthreads();

    // issue stage k (channels k*8..k*8+7) into slot k%STAGES
    auto issue = [&](int k) {
        const int slot = k % STAGES;
        const uint32_t dst = smem_base + slot * STAGE_BYTES;
        const uint32_t bar = mbar0 + slot * 8;
        mbar_expect_tx(bar, STAGE_BYTES);
        #pragma unroll
        for (int c = 0; c < CHPST; c++)
            bulk_ld(dst + c * (PIX_PER_CTA * 4),
                    src + (size_t)(k * CHPST + c) * HW,
                    PIX_PER_CTA * 4, bar);
    };
    if (tid == 0) { issue(0); issue(1); issue(2); }

    float a0 = 0.f, a1 = 0.f, a2 = 0.f, a3 = 0.f;
    #pragma unroll 1
    for (int i = 0; i < NSTG; i++) {
        const int slot = i % STAGES;
        mbar_wait(mbar0 + slot * 8, (i / STAGES) & 1);
        const float4* st = (const float4*)(smraw + slot * STAGE_BYTES);
        #pragma unroll
        for (int c = 0; c < CHPST; c++) {
            float4 v = st[c * (PIX_PER_CTA / 4) + tid];
            a0 = fmaf(v.x, v.x, a0);
            a1 = fmaf(v.y, v.y, a1);
            a2 = fmaf(v.z, v.z, a2);
            a3 = fmaf(v.w, v.w, a3);
        }
        __syncthreads();                       // all consumed before reissue
        if (tid == 0 && i + STAGES < NSTG) issue(i + STAGES);
    }

    float4 o;
    o.x = sqrtf(a0); o.y = sqrtf(a1); o.z = sqrtf(a2); o.w = sqrtf(a3);
    ((float4*)g_intensity[m])[s * (PIX_PER_CTA / 4) + tid] = o;
}

// ---------------------------------------------------------------------------
// Kernel 2: tail — UNCHANGED proven R6/R11 code. 128 CTAs x 256 thr.
// ---------------------------------------------------------------------------
__global__ void __launch_bounds__(T2, 2) tail_kernel(
    const float* __restrict__ det, const float* __restrict__ loc,
    float* __restrict__ out)
{
    __shared__ float sbuf[5120];
    float* rawp   = sbuf;
    float* masked = sbuf + 2560;
    float (*df)[CC] = (float(*)[CC])sbuf;
    float (*lf)[CC] = (float(*)[CC])(sbuf + 2560);

    __shared__ float s_wval[8][TOPK];
    __shared__ int   s_widx[8][TOPK];
    __shared__ float s_mv[2][JCTAS * TOPK];
    __shared__ int   s_mi[2][JCTAS * TOPK];
    __shared__ float s_dkv[TOPK], s_lkv[TOPK];
    __shared__ int   s_dki[TOPK], s_lki[TOPK];
    __shared__ float s_na[TOPK], s_nb[TOPK], s_ws[8];
    __shared__ unsigned s_flag;

    const int tid  = threadIdx.x;
    const int lane = tid & 31;
    const int w    = tid >> 5;
    const int m    = blockIdx.x >> 3;
    const int j    = blockIdx.x & 7;
    const int b    = m & 7;

    for (int i = tid; i < STG_ROWS * PADW; i += T2) rawp[i] = -CUDART_INF_F;
    __syncthreads();
    {
        const float* gi = g_intensity[m];
        for (int i = tid; i < STG_ROWS * WW; i += T2) {
            int r = i >> 7, x = i & 127;
            int grow = j * JROWS - 1 + r;
            if (grow >= 0 && grow < HH)
                rawp[r * PADW + x + 1] = __ldcg(&gi[(grow << 7) + x]);
        }
    }
    __syncthreads();

    for (int p = tid; p < JPIX; p += T2) {
        int yl = p >> 7, x = p & 127;
        const float* c = &rawp[(yl + 1) * PADW + (x + 1)];
        float v = c[0];
        float n0 = fmaxf(fmaxf(c[-PADW - 1], c[-PADW]), c[-PADW + 1]);
        float n1 = fmaxf(c[-1], c[1]);
        float n2 = fmaxf(fmaxf(c[PADW - 1], c[PADW]), c[PADW + 1]);
        float nmax = fmaxf(fmaxf(n0, n1), n2);
        masked[p] = (v > THRESH && v >= nmax) ? v : -CUDART_INF_F;
    }
    __syncthreads();

    {
        const int base = w * 256;
        for (int k = 0; k < TOPK; k++) {
            float bv = -CUDART_INF_F; int bp = 0x7fffffff;
            #pragma unroll
            for (int q = 0; q < 8; q++) {
                int p = base + q * 32 + lane;
                float v = masked[p];
                if (v > bv || (v == bv && p < bp)) { bv = v; bp = p; }
            }
            #pragma unroll
            for (int o = 16; o > 0; o >>= 1) {
                float v2 = __shfl_down_sync(0xffffffffu, bv, o);
                int   p2 = __shfl_down_sync(0xffffffffu, bp, o);
                if (v2 > bv || (v2 == bv && p2 < bp)) { bv = v2; bp = p2; }
            }
            bv = __shfl_sync(0xffffffffu, bv, 0);
            bp = __shfl_sync(0xffffffffu, bp, 0);
            if (lane == 0) {
                s_wval[w][k] = bv;
                s_widx[w][k] = j * JPIX + bp;
                masked[bp] = -CUDART_INF_F;
            }
            __syncwarp();
        }
    }
    __syncthreads();

    if (w == 0) {
        float* fv = &s_wval[0][0];
        int*   fi = &s_widx[0][0];
        for (int k = 0; k < TOPK; k++) {
            float bv = -CUDART_INF_F; int bi = 0x7fffffff; int bp = -1;
            #pragma unroll
            for (int q = 0; q < 3; q++) {
                int p = q * 32 + lane;
                if (p < 80) {
                    float v = fv[p]; int i = fi[p];
                    if (v > bv || (v == bv && i < bi)) { bv = v; bi = i; bp = p; }
                }
            }
            #pragma unroll
            for (int o = 16; o > 0; o >>= 1) {
                float v2 = __shfl_down_sync(0xffffffffu, bv, o);
                int   i2 = __shfl_down_sync(0xffffffffu, bi, o);
                int   p2 = __shfl_down_sync(0xffffffffu, bp, o);
                if (v2 > bv || (v2 == bv && i2 < bi)) { bv = v2; bi = i2; bp = p2; }
            }
            bp = __shfl_sync(0xffffffffu, bp, 0);
            if (lane == 0) {
                g_part_val[m][j][k] = bv;
                g_part_idx[m][j][k] = bi;
                if (bp >= 0) fv[bp] = -CUDART_INF_F;
            }
            __syncwarp();
        }
    }
    __syncthreads();
    if (tid == 0) {
        __threadfence();
        unsigned old = atomicAdd(&g_samp_cnt[b], 1u);
        if (old == 15u) g_samp_cnt[b] = 0u;
        s_flag = (old == 15u);
    }
    __syncthreads();
    if (!s_flag) return;

    __threadfence();
    if (w < 2) {
        const int mm = (w == 0) ? b : (8 + b);
        const float* pv = &g_part_val[mm][0][0];
        const int*   pi = &g_part_idx[mm][0][0];
        for (int p = lane; p < 80; p += 32) {
            s_mv[w][p] = __ldcg(&pv[p]);
            s_mi[w][p] = __ldcg(&pi[p]);
        }
        __syncwarp();
        for (int k = 0; k < TOPK; k++) {
            float bv = -CUDART_INF_F; int bi = 0x7fffffff; int bp = -1;
            #pragma unroll
            for (int q = 0; q < 3; q++) {
                int p = q * 32 + lane;
                if (p < 80) {
                    float v = s_mv[w][p]; int i = s_mi[w][p];
                    if (v > bv || (v == bv && i < bi)) { bv = v; bi = i; bp = p; }
                }
            }
            #pragma unroll
            for (int o = 16; o > 0; o >>= 1) {
                float v2 = __shfl_down_sync(0xffffffffu, bv, o);
                int   i2 = __shfl_down_sync(0xffffffffu, bi, o);
                int   p2 = __shfl_down_sync(0xffffffffu, bp, o);
                if (v2 > bv || (v2 == bv && i2 < bi)) { bv = v2; bi = i2; bp = p2; }
            }
            bp = __shfl_sync(0xffffffffu, bp, 0);
            if (lane == 0) {
                if (w == 0) { s_dkv[k] = bv; s_dki[k] = (bv > -CUDART_INF_F) ? bi : 0; }
                else        { s_lkv[k] = bv; s_lki[k] = (bv > -CUDART_INF_F) ? bi : 0; }
                if (bp >= 0) s_mv[w][bp] = -CUDART_INF_F;
            }
            __syncwarp();
        }
    }
    __syncthreads();

    {
        const float* dbase = det + (size_t)b * CC * HW;
        const float* lbase = loc + (size_t)b * CC * HW;
        for (int idx = tid; idx < TOPK * CC; idx += T2) {
            int k = idx >> 8, c = idx & 255;
            df[k][c] = __ldg(&dbase[(size_t)c * HW + s_dki[k]]);
            lf[k][c] = __ldg(&lbase[(size_t)c * HW + s_lki[k]]);
        }
    }
    __syncthreads();

    for (int k = w; k < TOPK; k += 8) {
        float sa = 0.f, sb = 0.f;
        #pragma unroll
        for (int c = lane; c < CC; c += 32) {
            sa = fmaf(df[k][c], df[k][c], sa);
            sb = fmaf(lf[k][c], lf[k][c], sb);
        }
        #pragma unroll
        for (int o = 16; o > 0; o >>= 1) {
            sa += __shfl_down_sync(0xffffffffu, sa, o);
            sb += __shfl_down_sync(0xffffffffu, sb, o);
        }
        if (lane == 0) {
            s_na[k] = fmaxf(sqrtf(sa), EPSV);
            s_nb[k] = fmaxf(sqrtf(sb), EPSV);
        }
    }
    __syncthreads();

    float lsum = 0.f;
    for (int p = w; p < TOPK * TOPK; p += 8) {
        int i = p / TOPK, jj = p % TOPK;
        float dot = 0.f;
        #pragma unroll
        for (int c = lane; c < CC; c += 32) dot = fmaf(df[i][c], lf[jj][c], dot);
        #pragma unroll
        for (int o = 16; o > 0; o >>= 1)
            dot += __shfl_down_sync(0xffffffffu, dot, o);
        if (lane == 0 && s_dkv[i] > -CUDART_INF_F && s_lkv[jj] > -CUDART_INF_F)
            lsum += fmaxf(dot / (s_na[i] * s_nb[jj]) - MARGIN, 0.f);
    }
    if (lane == 0) s_ws[w] = lsum;
    __syncthreads();

    if (tid == 0) {
        int nd = 0, nl = 0;
        #pragma unroll
        for (int k = 0; k < TOPK; k++) {
            nd += (s_dkv[k] > -CUDART_INF_F) ? 1 : 0;
            nl += (s_lkv[k] > -CUDART_INF_F) ? 1 : 0;
        }
        float ssum = 0.f;
        #pragma unroll
        for (int q = 0; q < 8; q++) ssum += s_ws[q];
        int np = nd * nl;
        g_losses[b] = (np > 0) ? (ssum / (float)np) : 0.f;

        __threadfence();
        unsigned old = atomicAdd(&g_done_cnt, 1u);
        if (old == (BB - 1)) {
            g_done_cnt = 0u;
            __threadfence();
            float tot = 0.f;
            #pragma unroll
            for (int q = 0; q < BB; q++) tot += __ldcg(&g_losses[q]);
            out[0] = tot / (float)BB;
        }
    }
}

extern "C" void kernel_launch(void* const* d_in, const int* in_sizes, int n_in,
                              void* d_out, int out_size)
{
    const float* loc = (const float*)d_in[0];   // loc_features [8,256,128,128]
    const float* det = (const float*)d_in[1];   // det_features [8,256,128,128]
    float* out = (float*)d_out;

    cudaFuncSetAttribute(stream_kernel,
                         cudaFuncAttributeMaxDynamicSharedMemorySize, SMEM_STREAM);
    stream_kernel<<<NMAPS * SLICES, 256, SMEM_STREAM>>>(det, loc);
    tail_kernel<<<NMAPS * JCTAS, T2>>>(det, loc, out);
}

// round 13
// speedup vs baseline: 1.0347x; 1.0347x over previous
#include <cuda_runtime.h>
#include <math_constants.h>
#include <cstdint>

#define BB 8
#define CC 256
#define HH 128
#define WW 128
#define HW (HH*WW)
#define TOPK 10
#define THRESH 0.5f
#define MARGIN 0.5f
#define EPSV 1e-8f
#define NMAPS 16
#define JCTAS 8                    // tail CTAs per map
#define JROWS 16
#define JPIX (JROWS*WW)            // 2048 pixels per region
#define PADW 130
#define STG_ROWS 18
#define T2 256
#define CAP 512                    // exact max strict-3x3-maxima in 16x128

// scratch (no allocations allowed); counters self-reset -> replay-safe
__device__ float    g_intensity[NMAPS][HW];
__device__ float    g_part_val[NMAPS][JCTAS][TOPK];
__device__ int      g_part_idx[NMAPS][JCTAS][TOPK];
__device__ float    g_losses[BB];
__device__ unsigned g_samp_cnt[BB];
__device__ unsigned g_done_cnt;

__device__ __forceinline__ unsigned redux_max_u32(unsigned v) {
    unsigned r;
    asm volatile("redux.sync.max.u32 %0, %1, 0xffffffff;" : "=r"(r) : "r"(v));
    return r;
}
__device__ __forceinline__ unsigned redux_min_u32(unsigned v) {
    unsigned r;
    asm volatile("redux.sync.min.u32 %0, %1, 0xffffffff;" : "=r"(r) : "r"(v));
    return r;
}

// ---------------------------------------------------------------------------
// Kernel 1: intensity stream — UNCHANGED from R11 (best: ~34us, near HBM
// roofline; TMA variant measured no better).
// ---------------------------------------------------------------------------
__global__ void __launch_bounds__(256, 2) intensity_kernel(
    const float* __restrict__ det, const float* __restrict__ loc)
{
    __shared__ float4 s_part[128];

    const int bid  = blockIdx.x;
    const int m    = bid >> 5;
    const int sl   = bid & 31;
    const int b    = m & 7;
    const int tid  = threadIdx.x;
    const int half = tid >> 7;
    const int gl   = tid & 127;
    const int g    = sl * 128 + gl;

    const float* src = (m < 8) ? det : loc;
    const float4* base = ((const float4*)(src + (size_t)b * CC * HW))
                         + g + (size_t)half * 128 * (HW / 4);

    float a0 = 0.f, a1 = 0.f, a2 = 0.f, a3 = 0.f;
    #pragma unroll 1
    for (int c0 = 0; c0 < 128; c0 += 8) {
        float4 v[8];
        #pragma unroll
        for (int i = 0; i < 8; i++)
            v[i] = __ldcs(base + (size_t)(c0 + i) * (HW / 4));
        #pragma unroll
        for (int i = 0; i < 8; i++) {
            a0 = fmaf(v[i].x, v[i].x, a0);
            a1 = fmaf(v[i].y, v[i].y, a1);
            a2 = fmaf(v[i].z, v[i].z, a2);
            a3 = fmaf(v[i].w, v[i].w, a3);
        }
    }
    if (half) s_part[gl] = make_float4(a0, a1, a2, a3);
    __syncthreads();
    if (!half) {
        float4 p = s_part[gl];
        float4 o;
        o.x = sqrtf(a0 + p.x);
        o.y = sqrtf(a1 + p.y);
        o.z = sqrtf(a2 + p.z);
        o.w = sqrtf(a3 + p.w);
        ((float4*)g_intensity[m])[g] = o;
    }
}

// ---------------------------------------------------------------------------
// Kernel 2: tail v3 — compact-then-select with redux.sync argmax.
// Detection appends peaks (~231 expected, cap 512 = exact theoretical max)
// to a block list; warp 0 runs 10 redux-argmax passes (2 redux ops each vs
// the old 5-level shfl cascades). Loss merges use the same redux path.
// ---------------------------------------------------------------------------
__global__ void __launch_bounds__(T2, 2) tail_kernel(
    const float* __restrict__ det, const float* __restrict__ loc,
    float* __restrict__ out)
{
    __shared__ float sbuf[5120];                  // 20KB, phase-aliased
    float* rawp   = sbuf;                         // 18*130 = 2340
    float* s_cval = sbuf + 2560;                  // CAP
    int*   s_cidx = (int*)(sbuf + 2560 + CAP);    // CAP
    float (*df)[CC] = (float(*)[CC])sbuf;         // loss alias
    float (*lf)[CC] = (float(*)[CC])(sbuf + 2560);// loss alias

    __shared__ float s_mv[2][JCTAS * TOPK];
    __shared__ int   s_mi[2][JCTAS * TOPK];
    __shared__ float s_dkv[TOPK], s_lkv[TOPK];
    __shared__ int   s_dki[TOPK], s_lki[TOPK];
    __shared__ float s_na[TOPK], s_nb[TOPK], s_ws[8];
    __shared__ int   s_cn;
    __shared__ unsigned s_flag;

    const int tid  = threadIdx.x;
    const int lane = tid & 31;
    const int w    = tid >> 5;                    // 8 warps
    const int m    = blockIdx.x >> 3;             // map 0..15
    const int j    = blockIdx.x & 7;              // region
    const int b    = m & 7;

    // ---- stage 16 rows + halo into padded smem (-inf border) ---------------
    for (int i = tid; i < STG_ROWS * PADW; i += T2) rawp[i] = -CUDART_INF_F;
    __syncthreads();
    {
        const float* gi = g_intensity[m];
        for (int i = tid; i < STG_ROWS * WW; i += T2) {
            int r = i >> 7, x = i & 127;
            int grow = j * JROWS - 1 + r;
            if (grow >= 0 && grow < HH)
                rawp[r * PADW + x + 1] = __ldcg(&gi[(grow << 7) + x]);
        }
        if (tid == 0) s_cn = 0;
    }
    __syncthreads();

    // ---- branch-free 3x3 strict maxima -> compact candidate list -----------
    for (int p = tid; p < JPIX; p += T2) {
        int yl = p >> 7, x = p & 127;
        const float* c = &rawp[(yl + 1) * PADW + (x + 1)];
        float v = c[0];
        float n0 = fmaxf(fmaxf(c[-PADW - 1], c[-PADW]), c[-PADW + 1]);
        float n1 = fmaxf(c[-1], c[1]);
        float n2 = fmaxf(fmaxf(c[PADW - 1], c[PADW]), c[PADW + 1]);
        float nmax = fmaxf(fmaxf(n0, n1), n2);
        if (v > THRESH && v >= nmax) {
            int s = atomicAdd(&s_cn, 1);          // s < CAP guaranteed
            s_cval[s] = v;
            s_cidx[s] = j * JPIX + p;             // global pixel index
        }
    }
    __syncthreads();

    // ---- warp 0: 10 redux-argmax passes (val desc, idx asc = lax.top_k) ----
    if (w == 0) {
        const int n = s_cn;
        for (int k = 0; k < TOPK; k++) {
            float bv = 0.f; int bi = 0x7fffffff; int bslot = -1;
            for (int p = lane; p < n; p += 32) {
                float v = s_cval[p];
                int   i = s_cidx[p];
                if (v > 0.f && (v > bv || (v == bv && i < bi))) {
                    bv = v; bi = i; bslot = p;
                }
            }
            unsigned vb = __float_as_uint(bv);    // >0 valid, 0 none
            unsigned mx = redux_max_u32(vb);
            unsigned ic = (vb == mx) ? (unsigned)bi : 0xffffffffu;
            unsigned wi = redux_min_u32(ic);
            if (mx != 0u && vb == mx && (unsigned)bi == wi)
                s_cval[bslot] = 0.f;              // consume winner
            if (lane == 0) {
                g_part_val[m][j][k] = (mx != 0u) ? __uint_as_float(mx)
                                                 : -CUDART_INF_F;
                g_part_idx[m][j][k] = (mx != 0u) ? (int)wi : 0;
            }
            __syncwarp();
        }
    }
    __syncthreads();
    if (tid == 0) {
        __threadfence();
        unsigned old = atomicAdd(&g_samp_cnt[b], 1u);
        if (old == 15u) g_samp_cnt[b] = 0u;       // reset for replay
        s_flag = (old == 15u);
    }
    __syncthreads();
    if (!s_flag) return;   // last of the sample's 16 region CTAs does the loss

    // ---- merge 80 partials per map via redux: warp0=det(b), warp1=loc(8+b) -
    __threadfence();
    if (w < 2) {
        const int mm = (w == 0) ? b : (8 + b);
        const float* pv = &g_part_val[mm][0][0];
        const int*   pi = &g_part_idx[mm][0][0];
        for (int p = lane; p < 80; p += 32) {
            s_mv[w][p] = __ldcg(&pv[p]);          // -inf = absent
            s_mi[w][p] = __ldcg(&pi[p]);
        }
        __syncwarp();
        for (int k = 0; k < TOPK; k++) {
            float bv = 0.f; int bi = 0x7fffffff; int bslot = -1;
            #pragma unroll
            for (int q = 0; q < 3; q++) {
                int p = q * 32 + lane;
                if (p < 80) {
                    float v = s_mv[w][p];
                    int   i = s_mi[w][p];
                    if (v > 0.f && (v > bv || (v == bv && i < bi))) {
                        bv = v; bi = i; bslot = p;
                    }
                }
            }
            unsigned vb = __float_as_uint(bv);
            unsigned mx = redux_max_u32(vb);
            unsigned ic = (vb == mx) ? (unsigned)bi : 0xffffffffu;
            unsigned wi = redux_min_u32(ic);
            if (mx != 0u && vb == mx && (unsigned)bi == wi)
                s_mv[w][bslot] = 0.f;
            if (lane == 0) {
                float fv = (mx != 0u) ? __uint_as_float(mx) : -CUDART_INF_F;
                int   fi = (mx != 0u) ? (int)wi : 0;
                if (w == 0) { s_dkv[k] = fv; s_dki[k] = fi; }
                else        { s_lkv[k] = fv; s_lki[k] = fi; }
            }
            __syncwarp();
        }
    }
    __syncthreads();   // candidate smem dead before alias overwrite

    // ---- gather features [10][256] x2 ---------------------------------------
    {
        const float* dbase = det + (size_t)b * CC * HW;
        const float* lbase = loc + (size_t)b * CC * HW;
        for (int idx = tid; idx < TOPK * CC; idx += T2) {
            int k = idx >> 8, c = idx & 255;
            df[k][c] = __ldg(&dbase[(size_t)c * HW + s_dki[k]]);
            lf[k][c] = __ldg(&lbase[(size_t)c * HW + s_lki[k]]);
        }
    }
    __syncthreads();

    // ---- norms (warp-per-row) ------------------------------------------------
    for (int k = w; k < TOPK; k += 8) {
        float sa = 0.f, sb = 0.f;
        #pragma unroll
        for (int c = lane; c < CC; c += 32) {
            sa = fmaf(df[k][c], df[k][c], sa);
            sb = fmaf(lf[k][c], lf[k][c], sb);
        }
        #pragma unroll
        for (int o = 16; o > 0; o >>= 1) {
            sa += __shfl_down_sync(0xffffffffu, sa, o);
            sb += __shfl_down_sync(0xffffffffu, sb, o);
        }
        if (lane == 0) {
            s_na[k] = fmaxf(sqrtf(sa), EPSV);
            s_nb[k] = fmaxf(sqrtf(sb), EPSV);
        }
    }
    __syncthreads();

    // ---- 100 pair dots over 8 warps ------------------------------------------
    float lsum = 0.f;
    for (int p = w; p < TOPK * TOPK; p += 8) {
        int i = p / TOPK, jj = p % TOPK;
        float dot = 0.f;
        #pragma unroll
        for (int c = lane; c < CC; c += 32) dot = fmaf(df[i][c], lf[jj][c], dot);
        #pragma unroll
        for (int o = 16; o > 0; o >>= 1)
            dot += __shfl_down_sync(0xffffffffu, dot, o);
        if (lane == 0 && s_dkv[i] > -CUDART_INF_F && s_lkv[jj] > -CUDART_INF_F)
            lsum += fmaxf(dot / (s_na[i] * s_nb[jj]) - MARGIN, 0.f);
    }
    if (lane == 0) s_ws[w] = lsum;
    __syncthreads();

    if (tid == 0) {
        int nd = 0, nl = 0;
        #pragma unroll
        for (int k = 0; k < TOPK; k++) {
            nd += (s_dkv[k] > -CUDART_INF_F) ? 1 : 0;
            nl += (s_lkv[k] > -CUDART_INF_F) ? 1 : 0;
        }
        float ssum = 0.f;
        #pragma unroll
        for (int q = 0; q < 8; q++) ssum += s_ws[q];
        int np = nd * nl;
        g_losses[b] = (np > 0) ? (ssum / (float)np) : 0.f;

        // last loss CTA writes the scalar (fixed-order sum, deterministic)
        __threadfence();
        unsigned old = atomicAdd(&g_done_cnt, 1u);
        if (old == (BB - 1)) {
            g_done_cnt = 0u;   // reset for replay
            __threadfence();
            float tot = 0.f;
            #pragma unroll
            for (int q = 0; q < BB; q++) tot += __ldcg(&g_losses[q]);
            out[0] = tot / (float)BB;
        }
    }
}

extern "C" void kernel_launch(void* const* d_in, const int* in_sizes, int n_in,
                              void* d_out, int out_size)
{
    const float* loc = (const float*)d_in[0];   // loc_features [8,256,128,128]
    const float* det = (const float*)d_in[1];   // det_features [8,256,128,128]
    float* out = (float*)d_out;

    intensity_kernel<<<512, 256>>>(det, loc);
    tail_kernel<<<NMAPS * JCTAS, T2>>>(det, loc, out);
}